// round 4
// baseline (speedup 1.0000x reference)
#include <cuda_runtime.h>

#define N_NODES 100000
#define N_EDGES 3200000
#define IN_DIM 64
#define HID_DIM 128
#define OUT_DIM 2
#define IN_VEC (IN_DIM / 4)       // 16 float4 per node row
#define HID_VEC (HID_DIM / 4)     // 32

// Scratch (device globals: allocation-free rule)
__device__ float  g_deg[N_NODES];
__device__ float  g_dinv[N_NODES];
__device__ float4 g_agg[N_NODES * IN_VEC];   // 25.6 MB, fits in L2

// ---------------------------------------------------------------------------
// Kernel 1: init degree to 1.0 (self-loop contribution)
__global__ void k_deg_init() {
    int i = blockIdx.x * blockDim.x + threadIdx.x;
    if (i < N_NODES) g_deg[i] = 1.0f;
}

// Kernel 2: accumulate in-degree over dst (edge_index is int32: JAX x64 off)
__global__ void k_deg_acc(const int* __restrict__ ei) {
    int i = blockIdx.x * blockDim.x + threadIdx.x;
    if (i < N_EDGES) {
        int d = ei[N_EDGES + i];
        if ((unsigned)d < N_NODES) atomicAdd(&g_deg[d], 1.0f);
    }
}

// Kernel 3: dinv = rsqrt(deg); agg[i] = x[i] * dinv[i]^2  (self-loop message)
__global__ void k_agg_init(const float4* __restrict__ x4) {
    int i = blockIdx.x * blockDim.x + threadIdx.x;
    if (i < N_NODES * IN_VEC) {
        int node = i >> 4;
        float d = rsqrtf(g_deg[node]);
        if ((i & 15) == 0) g_dinv[node] = d;
        float4 v = x4[i];
        float s = d * d;
        v.x *= s; v.y *= s; v.z *= s; v.w *= s;
        g_agg[i] = v;
    }
}

// Kernel 4: edge scatter in INPUT space (64-dim), 16 threads per edge.
// agg[dst] += x[src] * (dinv[src]*dinv[dst])  via 4 scalar REDG.ADD.F32
__global__ void k_edge(const int* __restrict__ ei,
                       const float4* __restrict__ x4) {
    int gi = blockIdx.x * blockDim.x + threadIdx.x;
    if (gi < N_EDGES * IN_VEC) {
        int e    = gi >> 4;
        int lane = gi & 15;
        int s = __ldg(&ei[e]);
        int t = __ldg(&ei[N_EDGES + e]);
        if ((unsigned)s >= N_NODES || (unsigned)t >= N_NODES) return;
        float norm = g_dinv[s] * g_dinv[t];
        float4 v = x4[s * IN_VEC + lane];
        float* p = (float*)&g_agg[t * IN_VEC + lane];
        atomicAdd(p + 0, v.x * norm);
        atomicAdd(p + 1, v.y * norm);
        atomicAdd(p + 2, v.z * norm);
        atomicAdd(p + 3, v.w * norm);
    }
}

// Kernel 5: out = relu(agg @ W_gcn + b_gcn) @ W_lin + b_lin
// One thread per node. W_gcn in smem (32 KB), LDS.128 broadcast -> 4 FMA/load.
__global__ __launch_bounds__(128)
void k_head(const float4* __restrict__ Wg4,  // [IN_DIM * HID_VEC] float4
            const float* __restrict__ bg,
            const float* __restrict__ Wl,    // [HID_DIM * 2]
            const float* __restrict__ bl,
            float2* __restrict__ out) {
    __shared__ float4 sW[IN_DIM * HID_VEC];   // 2048 float4 = 32 KB
    __shared__ float  sWl[HID_DIM * 2];
    __shared__ float  sbg[HID_DIM];

    int tid = threadIdx.x;
    for (int i = tid; i < IN_DIM * HID_VEC; i += blockDim.x) sW[i] = Wg4[i];
    for (int i = tid; i < HID_DIM * 2; i += blockDim.x) sWl[i] = Wl[i];
    for (int i = tid; i < HID_DIM; i += blockDim.x) sbg[i] = bg[i];
    __syncthreads();

    int node = blockIdx.x * blockDim.x + tid;
    if (node >= N_NODES) return;

    // Load this node's aggregated row into registers
    float a[IN_DIM];
    const float4* arow = &g_agg[node * IN_VEC];
#pragma unroll
    for (int k = 0; k < IN_VEC; k++) {
        float4 v = arow[k];
        a[4*k+0] = v.x; a[4*k+1] = v.y; a[4*k+2] = v.z; a[4*k+3] = v.w;
    }

    float o0 = bl[0], o1 = bl[1];
#pragma unroll 2
    for (int jq = 0; jq < HID_VEC; jq++) {
        float4 acc = make_float4(sbg[4*jq+0], sbg[4*jq+1],
                                 sbg[4*jq+2], sbg[4*jq+3]);
#pragma unroll
        for (int k = 0; k < IN_DIM; k++) {
            float4 w = sW[k * HID_VEC + jq];   // broadcast: all lanes same addr
            acc.x = fmaf(a[k], w.x, acc.x);
            acc.y = fmaf(a[k], w.y, acc.y);
            acc.z = fmaf(a[k], w.z, acc.z);
            acc.w = fmaf(a[k], w.w, acc.w);
        }
        acc.x = fmaxf(acc.x, 0.0f);
        acc.y = fmaxf(acc.y, 0.0f);
        acc.z = fmaxf(acc.z, 0.0f);
        acc.w = fmaxf(acc.w, 0.0f);
        int j = 4 * jq;
        o0 = fmaf(acc.x, sWl[2*(j+0)+0], o0);
        o1 = fmaf(acc.x, sWl[2*(j+0)+1], o1);
        o0 = fmaf(acc.y, sWl[2*(j+1)+0], o0);
        o1 = fmaf(acc.y, sWl[2*(j+1)+1], o1);
        o0 = fmaf(acc.z, sWl[2*(j+2)+0], o0);
        o1 = fmaf(acc.z, sWl[2*(j+2)+1], o1);
        o0 = fmaf(acc.w, sWl[2*(j+3)+0], o0);
        o1 = fmaf(acc.w, sWl[2*(j+3)+1], o1);
    }
    out[node] = make_float2(o0, o1);
}

// ---------------------------------------------------------------------------
extern "C" void kernel_launch(void* const* d_in, const int* in_sizes, int n_in,
                              void* d_out, int out_size) {
    const float* x  = (const float*)d_in[0];
    const int*   ei = (const int*)d_in[1];     // int32 (JAX default x64 off)
    const float* Wg = (const float*)d_in[2];
    const float* bg = (const float*)d_in[3];
    const float* Wl = (const float*)d_in[4];
    const float* bl = (const float*)d_in[5];
    float2*      out = (float2*)d_out;

    const float4* x4  = (const float4*)x;
    const float4* Wg4 = (const float4*)Wg;

    k_deg_init<<<(N_NODES + 255) / 256, 256>>>();
    k_deg_acc<<<(N_EDGES + 255) / 256, 256>>>(ei);
    k_agg_init<<<(N_NODES * IN_VEC + 255) / 256, 256>>>(x4);
    k_edge<<<(N_EDGES * IN_VEC + 255) / 256, 256>>>(ei, x4);
    k_head<<<(N_NODES + 127) / 128, 128>>>(Wg4, bg, Wl, bl, out);
}

// round 7
// speedup vs baseline: 1.9209x; 1.9209x over previous
#include <cuda_runtime.h>

#define N_NODES 100000
#define N_EDGES 3200000
#define IN_DIM 64
#define HID_DIM 128
#define OUT_DIM 2
#define IN_VEC (IN_DIM / 4)       // 16 float4 per node row
#define HID_VEC (HID_DIM / 4)     // 32

// Scratch (device globals: allocation-free rule)
__device__ float  g_deg[N_NODES];
__device__ float  g_dinv[N_NODES];
__device__ __align__(16) float4 g_agg[N_NODES * IN_VEC];   // 25.6 MB, fits in L2

// ---------------------------------------------------------------------------
// Kernel 1: init degree to 1.0 (self-loop contribution)
__global__ void k_deg_init() {
    int i = blockIdx.x * blockDim.x + threadIdx.x;
    if (i < N_NODES) g_deg[i] = 1.0f;
}

// Kernel 2: accumulate in-degree over dst (edge_index is int32: JAX x64 off)
__global__ void k_deg_acc(const int* __restrict__ ei) {
    int i = blockIdx.x * blockDim.x + threadIdx.x;
    if (i < N_EDGES) {
        int d = ei[N_EDGES + i];
        if ((unsigned)d < N_NODES) atomicAdd(&g_deg[d], 1.0f);
    }
}

// Kernel 3: dinv = rsqrt(deg); agg[i] = x[i] * dinv[i]^2  (self-loop message)
__global__ void k_agg_init(const float4* __restrict__ x4) {
    int i = blockIdx.x * blockDim.x + threadIdx.x;
    if (i < N_NODES * IN_VEC) {
        int node = i >> 4;
        float d = rsqrtf(g_deg[node]);
        if ((i & 15) == 0) g_dinv[node] = d;
        float4 v = x4[i];
        float s = d * d;
        v.x *= s; v.y *= s; v.z *= s; v.w *= s;
        g_agg[i] = v;
    }
}

// Kernel 4: edge scatter in INPUT space (64-dim), 16 threads per edge.
// agg[dst] += x[src] * (dinv[src]*dinv[dst])  via ONE red.global.add.v4.f32
// (4x fewer atomic instructions than scalar REDG.ADD.F32)
__global__ void k_edge(const int* __restrict__ ei,
                       const float4* __restrict__ x4) {
    int gi = blockIdx.x * blockDim.x + threadIdx.x;
    if (gi < N_EDGES * IN_VEC) {
        int e    = gi >> 4;
        int lane = gi & 15;
        int s = __ldg(&ei[e]);
        int t = __ldg(&ei[N_EDGES + e]);
        if ((unsigned)s >= N_NODES || (unsigned)t >= N_NODES) return;
        float norm = g_dinv[s] * g_dinv[t];
        float4 v = x4[s * IN_VEC + lane];
        v.x *= norm; v.y *= norm; v.z *= norm; v.w *= norm;
        float4* p = &g_agg[t * IN_VEC + lane];
        asm volatile("red.global.add.v4.f32 [%0], {%1,%2,%3,%4};"
                     :: "l"(p), "f"(v.x), "f"(v.y), "f"(v.z), "f"(v.w)
                     : "memory");
    }
}

// Kernel 5: out = relu(agg @ W_gcn + b_gcn) @ W_lin + b_lin
// One thread per node. W_gcn in smem (32 KB), LDS.128 broadcast -> 4 FMA/load.
__global__ __launch_bounds__(128)
void k_head(const float4* __restrict__ Wg4,  // [IN_DIM * HID_VEC] float4
            const float* __restrict__ bg,
            const float* __restrict__ Wl,    // [HID_DIM * 2]
            const float* __restrict__ bl,
            float2* __restrict__ out) {
    __shared__ float4 sW[IN_DIM * HID_VEC];   // 2048 float4 = 32 KB
    __shared__ float  sWl[HID_DIM * 2];
    __shared__ float  sbg[HID_DIM];

    int tid = threadIdx.x;
    for (int i = tid; i < IN_DIM * HID_VEC; i += blockDim.x) sW[i] = Wg4[i];
    for (int i = tid; i < HID_DIM * 2; i += blockDim.x) sWl[i] = Wl[i];
    for (int i = tid; i < HID_DIM; i += blockDim.x) sbg[i] = bg[i];
    __syncthreads();

    int node = blockIdx.x * blockDim.x + tid;
    if (node >= N_NODES) return;

    // Load this node's aggregated row into registers
    float a[IN_DIM];
    const float4* arow = &g_agg[node * IN_VEC];
#pragma unroll
    for (int k = 0; k < IN_VEC; k++) {
        float4 v = arow[k];
        a[4*k+0] = v.x; a[4*k+1] = v.y; a[4*k+2] = v.z; a[4*k+3] = v.w;
    }

    float o0 = bl[0], o1 = bl[1];
#pragma unroll 2
    for (int jq = 0; jq < HID_VEC; jq++) {
        float4 acc = make_float4(sbg[4*jq+0], sbg[4*jq+1],
                                 sbg[4*jq+2], sbg[4*jq+3]);
#pragma unroll
        for (int k = 0; k < IN_DIM; k++) {
            float4 w = sW[k * HID_VEC + jq];   // broadcast: all lanes same addr
            acc.x = fmaf(a[k], w.x, acc.x);
            acc.y = fmaf(a[k], w.y, acc.y);
            acc.z = fmaf(a[k], w.z, acc.z);
            acc.w = fmaf(a[k], w.w, acc.w);
        }
        acc.x = fmaxf(acc.x, 0.0f);
        acc.y = fmaxf(acc.y, 0.0f);
        acc.z = fmaxf(acc.z, 0.0f);
        acc.w = fmaxf(acc.w, 0.0f);
        int j = 4 * jq;
        o0 = fmaf(acc.x, sWl[2*(j+0)+0], o0);
        o1 = fmaf(acc.x, sWl[2*(j+0)+1], o1);
        o0 = fmaf(acc.y, sWl[2*(j+1)+0], o0);
        o1 = fmaf(acc.y, sWl[2*(j+1)+1], o1);
        o0 = fmaf(acc.z, sWl[2*(j+2)+0], o0);
        o1 = fmaf(acc.z, sWl[2*(j+2)+1], o1);
        o0 = fmaf(acc.w, sWl[2*(j+3)+0], o0);
        o1 = fmaf(acc.w, sWl[2*(j+3)+1], o1);
    }
    out[node] = make_float2(o0, o1);
}

// ---------------------------------------------------------------------------
extern "C" void kernel_launch(void* const* d_in, const int* in_sizes, int n_in,
                              void* d_out, int out_size) {
    const float* x  = (const float*)d_in[0];
    const int*   ei = (const int*)d_in[1];     // int32 (JAX default x64 off)
    const float* Wg = (const float*)d_in[2];
    const float* bg = (const float*)d_in[3];
    const float* Wl = (const float*)d_in[4];
    const float* bl = (const float*)d_in[5];
    float2*      out = (float2*)d_out;

    const float4* x4  = (const float4*)x;
    const float4* Wg4 = (const float4*)Wg;

    k_deg_init<<<(N_NODES + 255) / 256, 256>>>();
    k_deg_acc<<<(N_EDGES + 255) / 256, 256>>>(ei);
    k_agg_init<<<(N_NODES * IN_VEC + 255) / 256, 256>>>(x4);
    k_edge<<<(N_EDGES * IN_VEC + 255) / 256, 256>>>(ei, x4);
    k_head<<<(N_NODES + 127) / 128, 128>>>(Wg4, bg, Wl, bl, out);
}

// round 9
// speedup vs baseline: 2.5683x; 1.3370x over previous
#include <cuda_runtime.h>

#define N_NODES 100000
#define N_EDGES 3200000
#define IN_DIM 64
#define HID_DIM 128
#define OUT_DIM 2
#define IN_VEC (IN_DIM / 4)       // 16 float4 per node row
#define HID_VEC (HID_DIM / 4)     // 32

#define SCAN_CHUNK 1024
#define N_SCAN_BLOCKS ((N_NODES + SCAN_CHUNK - 1) / SCAN_CHUNK)   // 98

// Scratch (device globals: allocation-free rule)
__device__ __align__(16) int    g_cnt[N_NODES];
__device__ __align__(16) int    g_start[N_NODES];
__device__ __align__(16) int    g_cur[N_NODES];
__device__ __align__(16) float  g_dinv[N_NODES];
__device__ __align__(16) int    g_bsum[N_SCAN_BLOCKS];
__device__ __align__(16) float2 g_entry[N_EDGES];          // {src bits, norm} 25.6 MB
__device__ __align__(16) float4 g_agg[N_NODES * IN_VEC];   // 25.6 MB

// ---------------------------------------------------------------------------
__global__ void k_zero() {
    int i = blockIdx.x * blockDim.x + threadIdx.x;
    if (i < N_NODES) g_cnt[i] = 0;
}

// In-degree histogram (int reductions)
__global__ void k_count(const int* __restrict__ ei) {
    int i = blockIdx.x * blockDim.x + threadIdx.x;
    if (i < N_EDGES) {
        int d = ei[N_EDGES + i];
        if ((unsigned)d < N_NODES) atomicAdd(&g_cnt[d], 1);
    }
}

// Scan pass 1: per-block (1024 elems) exclusive scan of g_cnt into g_start,
// block totals to g_bsum. Also dinv = rsqrt(cnt+1) (self-loop incl).
__global__ __launch_bounds__(256)
void k_scan1() {
    __shared__ int s_sum[256];
    int b = blockIdx.x, t = threadIdx.x;
    int base = b * SCAN_CHUNK + t * 4;

    int c0 = 0, c1 = 0, c2 = 0, c3 = 0;
    if (base + 3 < N_NODES) {
        int4 c = *(const int4*)&g_cnt[base];
        c0 = c.x; c1 = c.y; c2 = c.z; c3 = c.w;
    } else {
        if (base + 0 < N_NODES) c0 = g_cnt[base + 0];
        if (base + 1 < N_NODES) c1 = g_cnt[base + 1];
        if (base + 2 < N_NODES) c2 = g_cnt[base + 2];
    }
    int s0 = c0, s1 = s0 + c1, s2 = s1 + c2, s3 = s2 + c3;
    s_sum[t] = s3;
    __syncthreads();
#pragma unroll
    for (int off = 1; off < 256; off <<= 1) {
        int v = 0;
        if (t >= off) v = s_sum[t - off];
        __syncthreads();
        if (t >= off) s_sum[t] += v;
        __syncthreads();
    }
    int excl = (t > 0) ? s_sum[t - 1] : 0;
    if (base + 0 < N_NODES) { g_start[base + 0] = excl;       g_dinv[base + 0] = rsqrtf((float)c0 + 1.0f); }
    if (base + 1 < N_NODES) { g_start[base + 1] = excl + s0;  g_dinv[base + 1] = rsqrtf((float)c1 + 1.0f); }
    if (base + 2 < N_NODES) { g_start[base + 2] = excl + s1;  g_dinv[base + 2] = rsqrtf((float)c2 + 1.0f); }
    if (base + 3 < N_NODES) { g_start[base + 3] = excl + s2;  g_dinv[base + 3] = rsqrtf((float)c3 + 1.0f); }
    if (t == 255) g_bsum[b] = s_sum[255];
}

// Scan pass 2: exclusive scan of the 98 block sums (single block)
__global__ __launch_bounds__(128)
void k_scan2() {
    __shared__ int s[128];
    int t = threadIdx.x;
    s[t] = (t < N_SCAN_BLOCKS) ? g_bsum[t] : 0;
    __syncthreads();
#pragma unroll
    for (int off = 1; off < 128; off <<= 1) {
        int v = 0;
        if (t >= off) v = s[t - off];
        __syncthreads();
        if (t >= off) s[t] += v;
        __syncthreads();
    }
    if (t < N_SCAN_BLOCKS) g_bsum[t] = (t > 0) ? s[t - 1] : 0;
}

// Scan pass 3: add block offsets; init write cursors
__global__ void k_scan3() {
    int i = blockIdx.x * blockDim.x + threadIdx.x;
    if (i < N_NODES) {
        int v = g_start[i] + g_bsum[i >> 10];
        g_start[i] = v;
        g_cur[i] = v;
    }
}

// Counting-sort fill: per-dst edge lists of packed {src, norm}
__global__ void k_scatter(const int* __restrict__ ei) {
    int i = blockIdx.x * blockDim.x + threadIdx.x;
    if (i < N_EDGES) {
        int s = ei[i];
        int t = ei[N_EDGES + i];
        if ((unsigned)s >= N_NODES || (unsigned)t >= N_NODES) return;
        float norm = g_dinv[s] * g_dinv[t];
        int slot = atomicAdd(&g_cur[t], 1);
        if ((unsigned)slot < N_EDGES)                 // clamp: corrupt -> wrong, not hang
            g_entry[slot] = make_float2(__int_as_float(s), norm);
    }
}

// Aggregate: 16 threads per node, register accumulation, ZERO float atomics.
// agg[node] = x[node]*dinv^2 + sum_{in-edges} x[src]*norm
__global__ __launch_bounds__(256)
void k_agg(const float4* __restrict__ x4) {
    int gi = blockIdx.x * blockDim.x + threadIdx.x;
    if (gi >= N_NODES * IN_VEC) return;
    int node = gi >> 4;
    int lane = gi & 15;

    float di = g_dinv[node];
    float sl = di * di;
    float4 acc = x4[node * IN_VEC + lane];
    acc.x *= sl; acc.y *= sl; acc.z *= sl; acc.w *= sl;

    // Hard-clamped bounds: any upstream corruption ends finitely.
    int j = g_start[node];
    if (j < 0) j = 0;
    int cnt = g_cnt[node];
    if (cnt < 0) cnt = 0;
    long long e64 = (long long)j + cnt;
    int end = (e64 > N_EDGES) ? N_EDGES : (int)e64;

    // Unroll x2 for MLP=2 on the gather
    for (; j + 1 < end; j += 2) {
        float2 en0 = g_entry[j];
        float2 en1 = g_entry[j + 1];
        int s0 = __float_as_int(en0.x);
        int s1 = __float_as_int(en1.x);
        if ((unsigned)s0 < N_NODES) {
            float4 v = __ldg(&x4[s0 * IN_VEC + lane]);
            acc.x = fmaf(v.x, en0.y, acc.x);
            acc.y = fmaf(v.y, en0.y, acc.y);
            acc.z = fmaf(v.z, en0.y, acc.z);
            acc.w = fmaf(v.w, en0.y, acc.w);
        }
        if ((unsigned)s1 < N_NODES) {
            float4 v = __ldg(&x4[s1 * IN_VEC + lane]);
            acc.x = fmaf(v.x, en1.y, acc.x);
            acc.y = fmaf(v.y, en1.y, acc.y);
            acc.z = fmaf(v.z, en1.y, acc.z);
            acc.w = fmaf(v.w, en1.y, acc.w);
        }
    }
    if (j < end) {
        float2 en = g_entry[j];
        int s0 = __float_as_int(en.x);
        if ((unsigned)s0 < N_NODES) {
            float4 v = __ldg(&x4[s0 * IN_VEC + lane]);
            acc.x = fmaf(v.x, en.y, acc.x);
            acc.y = fmaf(v.y, en.y, acc.y);
            acc.z = fmaf(v.z, en.y, acc.z);
            acc.w = fmaf(v.w, en.y, acc.w);
        }
    }
    g_agg[node * IN_VEC + lane] = acc;
}

// Head: out = relu(agg @ W_gcn + b_gcn) @ W_lin + b_lin
__global__ __launch_bounds__(128)
void k_head(const float4* __restrict__ Wg4,
            const float* __restrict__ bg,
            const float* __restrict__ Wl,
            const float* __restrict__ bl,
            float2* __restrict__ out) {
    __shared__ float4 sW[IN_DIM * HID_VEC];   // 32 KB
    __shared__ float  sWl[HID_DIM * 2];
    __shared__ float  sbg[HID_DIM];

    int tid = threadIdx.x;
    for (int i = tid; i < IN_DIM * HID_VEC; i += blockDim.x) sW[i] = Wg4[i];
    for (int i = tid; i < HID_DIM * 2; i += blockDim.x) sWl[i] = Wl[i];
    for (int i = tid; i < HID_DIM; i += blockDim.x) sbg[i] = bg[i];
    __syncthreads();

    int node = blockIdx.x * blockDim.x + tid;
    if (node >= N_NODES) return;

    float a[IN_DIM];
    const float4* arow = &g_agg[node * IN_VEC];
#pragma unroll
    for (int k = 0; k < IN_VEC; k++) {
        float4 v = arow[k];
        a[4*k+0] = v.x; a[4*k+1] = v.y; a[4*k+2] = v.z; a[4*k+3] = v.w;
    }

    float o0 = bl[0], o1 = bl[1];
#pragma unroll 2
    for (int jq = 0; jq < HID_VEC; jq++) {
        float4 acc = make_float4(sbg[4*jq+0], sbg[4*jq+1],
                                 sbg[4*jq+2], sbg[4*jq+3]);
#pragma unroll
        for (int k = 0; k < IN_DIM; k++) {
            float4 w = sW[k * HID_VEC + jq];
            acc.x = fmaf(a[k], w.x, acc.x);
            acc.y = fmaf(a[k], w.y, acc.y);
            acc.z = fmaf(a[k], w.z, acc.z);
            acc.w = fmaf(a[k], w.w, acc.w);
        }
        acc.x = fmaxf(acc.x, 0.0f);
        acc.y = fmaxf(acc.y, 0.0f);
        acc.z = fmaxf(acc.z, 0.0f);
        acc.w = fmaxf(acc.w, 0.0f);
        int j = 4 * jq;
        o0 = fmaf(acc.x, sWl[2*(j+0)+0], o0);
        o1 = fmaf(acc.x, sWl[2*(j+0)+1], o1);
        o0 = fmaf(acc.y, sWl[2*(j+1)+0], o0);
        o1 = fmaf(acc.y, sWl[2*(j+1)+1], o1);
        o0 = fmaf(acc.z, sWl[2*(j+2)+0], o0);
        o1 = fmaf(acc.z, sWl[2*(j+2)+1], o1);
        o0 = fmaf(acc.w, sWl[2*(j+3)+0], o0);
        o1 = fmaf(acc.w, sWl[2*(j+3)+1], o1);
    }
    out[node] = make_float2(o0, o1);
}

// ---------------------------------------------------------------------------
extern "C" void kernel_launch(void* const* d_in, const int* in_sizes, int n_in,
                              void* d_out, int out_size) {
    const float* x  = (const float*)d_in[0];
    const int*   ei = (const int*)d_in[1];     // int32 (JAX default x64 off)
    const float* Wg = (const float*)d_in[2];
    const float* bg = (const float*)d_in[3];
    const float* Wl = (const float*)d_in[4];
    const float* bl = (const float*)d_in[5];
    float2*      out = (float2*)d_out;

    const float4* x4  = (const float4*)x;
    const float4* Wg4 = (const float4*)Wg;

    k_zero   <<<(N_NODES + 255) / 256, 256>>>();
    k_count  <<<(N_EDGES + 255) / 256, 256>>>(ei);
    k_scan1  <<<N_SCAN_BLOCKS, 256>>>();
    k_scan2  <<<1, 128>>>();
    k_scan3  <<<(N_NODES + 255) / 256, 256>>>();
    k_scatter<<<(N_EDGES + 255) / 256, 256>>>(ei);
    k_agg    <<<(N_NODES * IN_VEC + 255) / 256, 256>>>(x4);
    k_head   <<<(N_NODES + 127) / 128, 128>>>(Wg4, bg, Wl, bl, out);
}